// round 15
// baseline (speedup 1.0000x reference)
#include <cuda_runtime.h>
#include <math.h>

#define B_   2
#define S_   2048
#define DM_  1024
#define H_   16
#define HD_  64
#define MTOT (B_*S_)

// Scratch (alloc-free rule: __device__ globals)
__device__ unsigned g_Qb[MTOT*DM_/2];   // bf16x2 packed, Q pre-scaled by 0.125
__device__ unsigned g_Kb[MTOT*DM_/2];
__device__ unsigned g_Vb[MTOT*DM_/2];
__device__ float    g_attn[MTOT*DM_];
__device__ float    g_x[MTOT*DM_];
__device__ unsigned long long g_mbits[(size_t)B_*S_*32];  // mask bits per 64-key tile

__device__ __forceinline__ unsigned f2tf(float f) {
    unsigned u; asm("cvt.rna.tf32.f32 %0, %1;" : "=r"(u) : "f"(f)); return u;
}

// pack two fp32 -> bf16x2 (lo = first arg, hi = second arg)
__device__ __forceinline__ unsigned packbf(float lo, float hi) {
    unsigned r; asm("cvt.rn.bf16x2.f32 %0, %1, %2;" : "=r"(r) : "f"(hi), "f"(lo));
    return r;
}

__device__ __forceinline__ void mma8(float* d, const unsigned* a, const unsigned* b, const float* c) {
    asm volatile("mma.sync.aligned.m16n8k8.row.col.f32.tf32.tf32.f32 "
        "{%0,%1,%2,%3}, {%4,%5,%6,%7}, {%8,%9}, {%10,%11,%12,%13};"
        : "=f"(d[0]), "=f"(d[1]), "=f"(d[2]), "=f"(d[3])
        : "r"(a[0]), "r"(a[1]), "r"(a[2]), "r"(a[3]),
          "r"(b[0]), "r"(b[1]),
          "f"(c[0]), "f"(c[1]), "f"(c[2]), "f"(c[3]));
}

// bf16 m16n8k16 mma, fp32 accumulate (in-place)
__device__ __forceinline__ void mma16(float* d, const unsigned* a, unsigned b0, unsigned b1) {
    asm volatile("mma.sync.aligned.m16n8k16.row.col.f32.bf16.bf16.f32 "
        "{%0,%1,%2,%3}, {%4,%5,%6,%7}, {%8,%9}, {%0,%1,%2,%3};"
        : "+f"(d[0]), "+f"(d[1]), "+f"(d[2]), "+f"(d[3])
        : "r"(a[0]), "r"(a[1]), "r"(a[2]), "r"(a[3]),
          "r"(b0), "r"(b1));
}

#define LDSM4(r0,r1,r2,r3, addr) \
    asm volatile("ldmatrix.sync.aligned.m8n8.x4.shared.b16 {%0,%1,%2,%3}, [%4];" \
        : "=r"(r0), "=r"(r1), "=r"(r2), "=r"(r3) : "r"(addr))
#define LDSM4T(r0,r1,r2,r3, addr) \
    asm volatile("ldmatrix.sync.aligned.m8n8.x4.trans.shared.b16 {%0,%1,%2,%3}, [%4];" \
        : "=r"(r0), "=r"(r1), "=r"(r2), "=r"(r3) : "r"(addr))

__device__ __forceinline__ void cpa16s(unsigned sa, const void* g) {
    asm volatile("cp.async.ca.shared.global [%0], [%1], 16;" :: "r"(sa), "l"(g));
}
#define CP_COMMIT() asm volatile("cp.async.commit_group;")
#define CP_WAIT(N)  asm volatile("cp.async.wait_group %0;" :: "n"(N))

// ---------------------------------------------------------------------------
// Mask -> bitmask pre-pass. One warp per (b,row): 32 ktiles, uint64 each from
// 64 ints via two ballots. ~32MB coalesced reads, ~15us.
// ---------------------------------------------------------------------------
__global__ __launch_bounds__(256)
void mask_bits(const int* __restrict__ mask)
{
    int gw = (blockIdx.x * blockDim.x + threadIdx.x) >> 5;   // global warp = row
    int lane = threadIdx.x & 31;
    if (gw >= B_*S_) return;
    const int* row = mask + (size_t)gw * S_;
    for (int kt = 0; kt < 32; kt++) {
        int m0 = row[kt*64 + lane];
        int m1 = row[kt*64 + 32 + lane];
        unsigned b0 = __ballot_sync(0xffffffffu, m0 != 0);
        unsigned b1 = __ballot_sync(0xffffffffu, m1 != 0);
        if (lane == 0)
            g_mbits[(size_t)gw*32 + kt] =
                (unsigned long long)b0 | ((unsigned long long)b1 << 32);
    }
}

// ---------------------------------------------------------------------------
// tf32 tensor-core GEMM (NT) — R13 body; epilogue stores bf16x2 for Q/K/V
// (Q pre-scaled 0.125), fp32 (+residual) for the output projection.
// ---------------------------------------------------------------------------
template<bool ADD_RES>
__global__ __launch_bounds__(256)
void tgemm(const float* __restrict__ A, const float* __restrict__ W,
           const float* __restrict__ bias, const float* __restrict__ res, int which)
{
    __shared__ unsigned As[128*36];
    __shared__ unsigned Bs[128*36];

    const float* Abase = (A == nullptr) ? (const float*)g_attn : A;

    const int tid = threadIdx.x;
    const int warp = tid >> 5, lane = tid & 31;
    const int g = lane >> 2, t = lane & 3;
    const int wm = warp >> 2, wn = warp & 3;
    const int m0 = blockIdx.y * 128, n0 = blockIdx.x * 128;

    float acc[4][4][4];
    #pragma unroll
    for (int mt = 0; mt < 4; mt++)
        #pragma unroll
        for (int nt = 0; nt < 4; nt++)
            #pragma unroll
            for (int i = 0; i < 4; i++) acc[mt][nt][i] = 0.f;

    for (int k0 = 0; k0 < DM_; k0 += 32) {
        __syncthreads();
        #pragma unroll
        for (int i = 0; i < 4; i++) {
            int idx = tid + i*256;
            int r = idx >> 3, c = (idx & 7) << 2;
            float4 a4 = *(const float4*)(Abase + (size_t)(m0 + r)*DM_ + k0 + c);
            float4 w4 = *(const float4*)(W     + (size_t)(n0 + r)*DM_ + k0 + c);
            uint4 at; at.x = f2tf(a4.x); at.y = f2tf(a4.y); at.z = f2tf(a4.z); at.w = f2tf(a4.w);
            uint4 wt; wt.x = f2tf(w4.x); wt.y = f2tf(w4.y); wt.z = f2tf(w4.z); wt.w = f2tf(w4.w);
            *(uint4*)&As[r*36 + c] = at;
            *(uint4*)&Bs[r*36 + c] = wt;
        }
        __syncthreads();

        #pragma unroll
        for (int ks = 0; ks < 4; ks++) {
            unsigned af[4][4], bf[4][2];
            #pragma unroll
            for (int mt = 0; mt < 4; mt++) {
                int base = (wm*64 + mt*16 + g)*36 + ks*8 + t;
                af[mt][0] = As[base];
                af[mt][1] = As[base + 8*36];
                af[mt][2] = As[base + 4];
                af[mt][3] = As[base + 8*36 + 4];
            }
            #pragma unroll
            for (int nt = 0; nt < 4; nt++) {
                int base = (wn*32 + nt*8 + g)*36 + ks*8 + t;
                bf[nt][0] = Bs[base];
                bf[nt][1] = Bs[base + 4];
            }
            #pragma unroll
            for (int mt = 0; mt < 4; mt++)
                #pragma unroll
                for (int nt = 0; nt < 4; nt++)
                    mma8(acc[mt][nt], af[mt], bf[nt], acc[mt][nt]);
        }
    }

    unsigned* Cb = (which == 0) ? g_Qb : (which == 1 ? g_Kb : g_Vb);
    const float sc = (which == 0) ? 0.125f : 1.0f;

    #pragma unroll
    for (int mt = 0; mt < 4; mt++) {
        int row = m0 + wm*64 + mt*16 + g;
        #pragma unroll
        for (int nt = 0; nt < 4; nt++) {
            int col = n0 + wn*32 + nt*8 + 2*t;
            float2 bv = *(const float2*)&bias[col];
            float v0 = acc[mt][nt][0] + bv.x, v1 = acc[mt][nt][1] + bv.y;
            float v2 = acc[mt][nt][2] + bv.x, v3 = acc[mt][nt][3] + bv.y;
            if (ADD_RES) {
                float2 r0 = *(const float2*)&res[(size_t)row*DM_ + col];
                float2 r1 = *(const float2*)&res[(size_t)(row+8)*DM_ + col];
                v0 += r0.x; v1 += r0.y; v2 += r1.x; v3 += r1.y;
                *(float2*)&g_x[(size_t)row*DM_ + col]     = make_float2(v0, v1);
                *(float2*)&g_x[(size_t)(row+8)*DM_ + col] = make_float2(v2, v3);
            } else {
                Cb[((size_t)row*DM_ + col) >> 1]     = packbf(v0*sc, v1*sc);
                Cb[((size_t)(row+8)*DM_ + col) >> 1] = packbf(v2*sc, v3*sc);
            }
        }
    }
}

// ---------------------------------------------------------------------------
// Flash attention, bf16 m16n8k16, register-resident P, cp.async double-buffer.
// Q/K/V already bf16 in global: fill = pure cp.async (no temp regs, no cvt).
// smem rows 128B data + 16B pad (stride 144B): LDSM phases conflict-free.
// Mask via g_mbits; all-ones tiles skip apply entirely.
// Block = 128 threads (4 warps), 64 q-rows, 64-key tiles. smem 36.9 KB.
// ---------------------------------------------------------------------------
#define KVST   144
#define KVTILE (64*KVST)

__global__ __launch_bounds__(128)
void flash_tc()
{
    __shared__ __align__(16) unsigned char smemb[4*KVTILE];  // K0 | K1 | V0 | V1
    const unsigned sb = (unsigned)__cvta_generic_to_shared(smemb);

    const int tid = threadIdx.x;
    const int warp = tid >> 5, lane = tid & 31;
    const int g = lane >> 2, t = lane & 3;
    const int q0 = blockIdx.x * 64;
    const int bh = blockIdx.y, b = bh >> 4, h = bh & 15;
    const int wq = warp * 16;

    // fill assignment: half-row (64B) per thread
    const int fr = tid >> 1;
    const int fc = (tid & 1) * 64;
    const unsigned fdst = fr*KVST + fc;

    const char* qsrc = (const char*)g_Qb + ((size_t)(b*S_ + q0 + fr)*DM_ + h*HD_)*2 + fc;
    const char* ksrc = (const char*)g_Kb + ((size_t)(b*S_ + fr)*DM_ + h*HD_)*2 + fc;
    const char* vsrc = (const char*)g_Vb + ((size_t)(b*S_ + fr)*DM_ + h*HD_)*2 + fc;

    // Stage Q into buffer K1 (group 0), KV tile 0 into K0/V0 (group 1).
    #pragma unroll
    for (int j = 0; j < 4; j++)
        cpa16s(sb + KVTILE + fdst + j*16, qsrc + j*16);
    CP_COMMIT();
    #pragma unroll
    for (int j = 0; j < 4; j++) {
        cpa16s(sb + fdst + j*16,            ksrc + j*16);
        cpa16s(sb + 2*KVTILE + fdst + j*16, vsrc + j*16);
    }
    CP_COMMIT();

    CP_WAIT(1);
    __syncthreads();

    // qf via ldmatrix from staged Q (buffer K1)
    unsigned qf[4][4];
    {
        unsigned qbase = sb + KVTILE
            + (wq + (lane & 7) + ((lane >> 3) & 1)*8)*KVST + ((lane >> 4) & 1)*16;
        #pragma unroll
        for (int ks = 0; ks < 4; ks++)
            LDSM4(qf[ks][0], qf[ks][1], qf[ks][2], qf[ks][3], qbase + ks*32);
    }

    float o[8][4];
    #pragma unroll
    for (int nt = 0; nt < 8; nt++)
        #pragma unroll
        for (int i = 0; i < 4; i++) o[nt][i] = 0.f;
    float mi[2] = {-1e30f, -1e30f}, li[2] = {0.f, 0.f};

    const unsigned long long* mrow = g_mbits + (size_t)(b*S_ + q0 + wq + g)*32;

    const unsigned kladdr = ((lane & 7) + ((lane >> 4) & 1)*8)*KVST + ((lane >> 3) & 1)*16;
    const unsigned vladdr = ((lane & 7) + ((lane >> 3) & 1)*8)*KVST + ((lane >> 4) & 1)*16;

    for (int i = 0; i < 32; i++) {
        CP_WAIT(0);
        __syncthreads();   // all copies landed AND prev compute done

        const unsigned off = (i & 1) ? KVTILE : 0u;
        if (i + 1 < 32) {
            const unsigned noff = (i & 1) ? 0u : KVTILE;
            const char* nk = ksrc + (size_t)(i + 1)*64*(DM_*2);
            const char* nv = vsrc + (size_t)(i + 1)*64*(DM_*2);
            #pragma unroll
            for (int j = 0; j < 4; j++) {
                cpa16s(sb + noff + fdst + j*16,            nk + j*16);
                cpa16s(sb + 2*KVTILE + noff + fdst + j*16, nv + j*16);
            }
            CP_COMMIT();
        }

        const unsigned Kbuf = sb + off;
        const unsigned Vbuf = sb + 2*KVTILE + off;

        // S = Q K^T
        float s[8][4];
        #pragma unroll
        for (int nt = 0; nt < 8; nt++)
            #pragma unroll
            for (int ii = 0; ii < 4; ii++) s[nt][ii] = 0.f;

        #pragma unroll
        for (int ks = 0; ks < 4; ks++) {
            #pragma unroll
            for (int ntp = 0; ntp < 4; ntp++) {
                unsigned k0r, k1r, k2r, k3r;
                LDSM4(k0r, k1r, k2r, k3r, Kbuf + kladdr + ntp*16*KVST + ks*32);
                mma16(s[2*ntp],   qf[ks], k0r, k1r);
                mma16(s[2*ntp+1], qf[ks], k2r, k3r);
            }
        }

        // Mask (bitmask; all-ones tiles skip)
        {
            unsigned long long mb0 = mrow[i];
            unsigned long long mb1 = mrow[8*32 + i];
            if (mb0 != ~0ull) {
                #pragma unroll
                for (int nt = 0; nt < 8; nt++) {
                    if (!((mb0 >> (nt*8 + 2*t))     & 1)) s[nt][0] = -1e9f;
                    if (!((mb0 >> (nt*8 + 2*t + 1)) & 1)) s[nt][1] = -1e9f;
                }
            }
            if (mb1 != ~0ull) {
                #pragma unroll
                for (int nt = 0; nt < 8; nt++) {
                    if (!((mb1 >> (nt*8 + 2*t))     & 1)) s[nt][2] = -1e9f;
                    if (!((mb1 >> (nt*8 + 2*t + 1)) & 1)) s[nt][3] = -1e9f;
                }
            }
        }

        // Online softmax (rows g, g+8)
        #pragma unroll
        for (int rr = 0; rr < 2; rr++) {
            float mx = -1e30f;
            #pragma unroll
            for (int nt = 0; nt < 8; nt++)
                mx = fmaxf(mx, fmaxf(s[nt][2*rr], s[nt][2*rr+1]));
            mx = fmaxf(mx, __shfl_xor_sync(0xffffffffu, mx, 1));
            mx = fmaxf(mx, __shfl_xor_sync(0xffffffffu, mx, 2));
            float mnew = fmaxf(mi[rr], mx);
            float alpha = __expf(mi[rr] - mnew);
            float sum = 0.f;
            #pragma unroll
            for (int nt = 0; nt < 8; nt++) {
                s[nt][2*rr]   = __expf(s[nt][2*rr]   - mnew);
                s[nt][2*rr+1] = __expf(s[nt][2*rr+1] - mnew);
                sum += s[nt][2*rr] + s[nt][2*rr+1];
            }
            sum += __shfl_xor_sync(0xffffffffu, sum, 1);
            sum += __shfl_xor_sync(0xffffffffu, sum, 2);
            li[rr] = li[rr]*alpha + sum;
            mi[rr] = mnew;
            #pragma unroll
            for (int nt = 0; nt < 8; nt++) {
                o[nt][2*rr]   *= alpha;
                o[nt][2*rr+1] *= alpha;
            }
        }

        // O += P V : P packed from C-frags in registers
        #pragma unroll
        for (int ks = 0; ks < 4; ks++) {
            unsigned pa[4];
            pa[0] = packbf(s[2*ks][0],   s[2*ks][1]);
            pa[1] = packbf(s[2*ks][2],   s[2*ks][3]);
            pa[2] = packbf(s[2*ks+1][0], s[2*ks+1][1]);
            pa[3] = packbf(s[2*ks+1][2], s[2*ks+1][3]);
            #pragma unroll
            for (int ntp = 0; ntp < 4; ntp++) {
                unsigned v0r, v1r, v2r, v3r;
                LDSM4T(v0r, v1r, v2r, v3r, Vbuf + vladdr + ks*16*KVST + ntp*32);
                mma16(o[2*ntp],   pa, v0r, v1r);
                mma16(o[2*ntp+1], pa, v2r, v3r);
            }
        }
    }

    // Epilogue
    float inv0 = 1.f / li[0], inv1 = 1.f / li[1];
    float* dst0 = g_attn + ((size_t)(b*S_ + q0 + wq + g))*DM_ + h*HD_;
    float* dst1 = dst0 + (size_t)8*DM_;
    #pragma unroll
    for (int nt = 0; nt < 8; nt++) {
        int c = nt*8 + 2*t;
        *(float2*)&dst0[c] = make_float2(o[nt][0]*inv0, o[nt][1]*inv0);
        *(float2*)&dst1[c] = make_float2(o[nt][2]*inv1, o[nt][3]*inv1);
    }
}

// ---------------------------------------------------------------------------
// LayerNorm: unbiased std (ddof=1), denominator (std + eps). One block per row.
// ---------------------------------------------------------------------------
__global__ __launch_bounds__(256)
void layernorm(const float* __restrict__ gamma, const float* __restrict__ beta,
               float* __restrict__ out)
{
    __shared__ float red[2][8];
    const int row = blockIdx.x;
    const int tid = threadIdx.x;
    const float* xr = g_x + (size_t)row * DM_;
    const int c = tid * 4;

    float4 xv = *(const float4*)(xr + c);
    float sum = xv.x + xv.y + xv.z + xv.w;
    float sq  = xv.x*xv.x + xv.y*xv.y + xv.z*xv.z + xv.w*xv.w;

    #pragma unroll
    for (int off = 16; off > 0; off >>= 1) {
        sum += __shfl_xor_sync(0xffffffffu, sum, off);
        sq  += __shfl_xor_sync(0xffffffffu, sq,  off);
    }
    const int w = tid >> 5, lane = tid & 31;
    if (lane == 0) { red[0][w] = sum; red[1][w] = sq; }
    __syncthreads();
    if (tid == 0) {
        float s = 0.f, q = 0.f;
        #pragma unroll
        for (int i = 0; i < 8; i++) { s += red[0][i]; q += red[1][i]; }
        red[0][0] = s; red[1][0] = q;
    }
    __syncthreads();
    sum = red[0][0]; sq = red[1][0];

    float mean = sum / (float)DM_;
    float var  = (sq - (float)DM_ * mean * mean) / (float)(DM_ - 1);
    var = fmaxf(var, 0.f);
    float inv = 1.f / (sqrtf(var) + 1e-6f);

    float4 g4 = *(const float4*)(gamma + c);
    float4 b4 = *(const float4*)(beta + c);
    float4 ov;
    ov.x = g4.x * (xv.x - mean) * inv + b4.x;
    ov.y = g4.y * (xv.y - mean) * inv + b4.y;
    ov.z = g4.z * (xv.z - mean) * inv + b4.z;
    ov.w = g4.w * (xv.w - mean) * inv + b4.w;
    *(float4*)(out + (size_t)row * DM_ + c) = ov;
}

// ---------------------------------------------------------------------------
extern "C" void kernel_launch(void* const* d_in, const int* in_sizes, int n_in,
                              void* d_out, int out_size)
{
    (void)in_sizes; (void)n_in; (void)out_size;
    const float* query = (const float*)d_in[0];
    const float* key_  = (const float*)d_in[1];
    const float* value = (const float*)d_in[2];
    const int*   mask  = (const int*)  d_in[3];
    const float* Wq = (const float*)d_in[4];
    const float* bq = (const float*)d_in[5];
    const float* Wk = (const float*)d_in[6];
    const float* bk = (const float*)d_in[7];
    const float* Wv = (const float*)d_in[8];
    const float* bv = (const float*)d_in[9];
    const float* Wo = (const float*)d_in[10];
    const float* bo = (const float*)d_in[11];
    const float* gamma = (const float*)d_in[12];
    const float* beta  = (const float*)d_in[13];
    float* out = (float*)d_out;

    mask_bits<<<(B_*S_*32 + 255)/256, 256>>>(mask);

    dim3 gg(DM_/128, MTOT/128);   // (8, 32)
    tgemm<false><<<gg, 256>>>(query, Wq, bq, nullptr, 0);
    tgemm<false><<<gg, 256>>>(key_,  Wk, bk, nullptr, 1);
    tgemm<false><<<gg, 256>>>(value, Wv, bv, nullptr, 2);

    flash_tc<<<dim3(S_/64, B_*H_), 128>>>();

    tgemm<true><<<gg, 256>>>(nullptr, Wo, bo, query, 3);

    layernorm<<<MTOT, 256>>>(gamma, beta, out);
}

// round 16
// speedup vs baseline: 1.1816x; 1.1816x over previous
#include <cuda_runtime.h>
#include <math.h>

#define B_   2
#define S_   2048
#define DM_  1024
#define H_   16
#define HD_  64
#define MTOT (B_*S_)

// Scratch (alloc-free rule: __device__ globals)
__device__ unsigned g_Qb[MTOT*DM_/2];   // bf16x2 packed, Q pre-scaled by 0.125
__device__ unsigned g_Kb[MTOT*DM_/2];
__device__ unsigned g_Vb[MTOT*DM_/2];
__device__ float    g_attn[MTOT*DM_];
__device__ float    g_x[MTOT*DM_];
__device__ unsigned long long g_mbits[(size_t)B_*S_*32];  // mask bits per 64-key tile

__device__ __forceinline__ unsigned f2tf(float f) {
    unsigned u; asm("cvt.rna.tf32.f32 %0, %1;" : "=r"(u) : "f"(f)); return u;
}

// pack two fp32 -> bf16x2 (lo = first arg, hi = second arg)
__device__ __forceinline__ unsigned packbf(float lo, float hi) {
    unsigned r; asm("cvt.rn.bf16x2.f32 %0, %1, %2;" : "=r"(r) : "f"(hi), "f"(lo));
    return r;
}

__device__ __forceinline__ void mma8(float* d, const unsigned* a, const unsigned* b, const float* c) {
    asm volatile("mma.sync.aligned.m16n8k8.row.col.f32.tf32.tf32.f32 "
        "{%0,%1,%2,%3}, {%4,%5,%6,%7}, {%8,%9}, {%10,%11,%12,%13};"
        : "=f"(d[0]), "=f"(d[1]), "=f"(d[2]), "=f"(d[3])
        : "r"(a[0]), "r"(a[1]), "r"(a[2]), "r"(a[3]),
          "r"(b[0]), "r"(b[1]),
          "f"(c[0]), "f"(c[1]), "f"(c[2]), "f"(c[3]));
}

// bf16 m16n8k16 mma, fp32 accumulate (in-place)
__device__ __forceinline__ void mma16(float* d, const unsigned* a, unsigned b0, unsigned b1) {
    asm volatile("mma.sync.aligned.m16n8k16.row.col.f32.bf16.bf16.f32 "
        "{%0,%1,%2,%3}, {%4,%5,%6,%7}, {%8,%9}, {%0,%1,%2,%3};"
        : "+f"(d[0]), "+f"(d[1]), "+f"(d[2]), "+f"(d[3])
        : "r"(a[0]), "r"(a[1]), "r"(a[2]), "r"(a[3]),
          "r"(b0), "r"(b1));
}

#define LDSM4(r0,r1,r2,r3, addr) \
    asm volatile("ldmatrix.sync.aligned.m8n8.x4.shared.b16 {%0,%1,%2,%3}, [%4];" \
        : "=r"(r0), "=r"(r1), "=r"(r2), "=r"(r3) : "r"(addr))
#define LDSM4T(r0,r1,r2,r3, addr) \
    asm volatile("ldmatrix.sync.aligned.m8n8.x4.trans.shared.b16 {%0,%1,%2,%3}, [%4];" \
        : "=r"(r0), "=r"(r1), "=r"(r2), "=r"(r3) : "r"(addr))

__device__ __forceinline__ void cpa16s(unsigned sa, const void* g) {
    asm volatile("cp.async.ca.shared.global [%0], [%1], 16;" :: "r"(sa), "l"(g));
}
#define CP_COMMIT() asm volatile("cp.async.commit_group;")
#define CP_WAIT(N)  asm volatile("cp.async.wait_group %0;" :: "n"(N))

// ---------------------------------------------------------------------------
// Mask -> bitmask pre-pass. One warp per (b,row): 32 ktiles, uint64 each from
// 64 ints via two ballots. ~32MB coalesced reads, ~15us.
// ---------------------------------------------------------------------------
__global__ __launch_bounds__(256)
void mask_bits(const int* __restrict__ mask)
{
    int gw = (blockIdx.x * blockDim.x + threadIdx.x) >> 5;   // global warp = row
    int lane = threadIdx.x & 31;
    if (gw >= B_*S_) return;
    const int* row = mask + (size_t)gw * S_;
    for (int kt = 0; kt < 32; kt++) {
        int m0 = row[kt*64 + lane];
        int m1 = row[kt*64 + 32 + lane];
        unsigned b0 = __ballot_sync(0xffffffffu, m0 != 0);
        unsigned b1 = __ballot_sync(0xffffffffu, m1 != 0);
        if (lane == 0)
            g_mbits[(size_t)gw*32 + kt] =
                (unsigned long long)b0 | ((unsigned long long)b1 << 32);
    }
}

// ---------------------------------------------------------------------------
// tf32 tensor-core GEMM (NT) — R13 body; epilogue stores bf16x2 for Q/K/V
// (Q pre-scaled 0.125), fp32 (+residual) for the output projection.
// __launch_bounds__(256, 2): cap regs at 128 so 2 blocks/SM fit (R15 ran at
// 138 regs -> 1 block/SM -> occ 12.5% -> 111us/launch; spills, if any, land
// in the cold epilogue).
// ---------------------------------------------------------------------------
template<bool ADD_RES>
__global__ __launch_bounds__(256, 2)
void tgemm(const float* __restrict__ A, const float* __restrict__ W,
           const float* __restrict__ bias, const float* __restrict__ res, int which)
{
    __shared__ unsigned As[128*36];
    __shared__ unsigned Bs[128*36];

    const float* Abase = (A == nullptr) ? (const float*)g_attn : A;

    const int tid = threadIdx.x;
    const int warp = tid >> 5, lane = tid & 31;
    const int g = lane >> 2, t = lane & 3;
    const int wm = warp >> 2, wn = warp & 3;
    const int m0 = blockIdx.y * 128, n0 = blockIdx.x * 128;

    float acc[4][4][4];
    #pragma unroll
    for (int mt = 0; mt < 4; mt++)
        #pragma unroll
        for (int nt = 0; nt < 4; nt++)
            #pragma unroll
            for (int i = 0; i < 4; i++) acc[mt][nt][i] = 0.f;

    for (int k0 = 0; k0 < DM_; k0 += 32) {
        __syncthreads();
        #pragma unroll
        for (int i = 0; i < 4; i++) {
            int idx = tid + i*256;
            int r = idx >> 3, c = (idx & 7) << 2;
            float4 a4 = *(const float4*)(Abase + (size_t)(m0 + r)*DM_ + k0 + c);
            float4 w4 = *(const float4*)(W     + (size_t)(n0 + r)*DM_ + k0 + c);
            uint4 at; at.x = f2tf(a4.x); at.y = f2tf(a4.y); at.z = f2tf(a4.z); at.w = f2tf(a4.w);
            uint4 wt; wt.x = f2tf(w4.x); wt.y = f2tf(w4.y); wt.z = f2tf(w4.z); wt.w = f2tf(w4.w);
            *(uint4*)&As[r*36 + c] = at;
            *(uint4*)&Bs[r*36 + c] = wt;
        }
        __syncthreads();

        #pragma unroll
        for (int ks = 0; ks < 4; ks++) {
            unsigned af[4][4], bf[4][2];
            #pragma unroll
            for (int mt = 0; mt < 4; mt++) {
                int base = (wm*64 + mt*16 + g)*36 + ks*8 + t;
                af[mt][0] = As[base];
                af[mt][1] = As[base + 8*36];
                af[mt][2] = As[base + 4];
                af[mt][3] = As[base + 8*36 + 4];
            }
            #pragma unroll
            for (int nt = 0; nt < 4; nt++) {
                int base = (wn*32 + nt*8 + g)*36 + ks*8 + t;
                bf[nt][0] = Bs[base];
                bf[nt][1] = Bs[base + 4];
            }
            #pragma unroll
            for (int mt = 0; mt < 4; mt++)
                #pragma unroll
                for (int nt = 0; nt < 4; nt++)
                    mma8(acc[mt][nt], af[mt], bf[nt], acc[mt][nt]);
        }
    }

    unsigned* Cb = (which == 0) ? g_Qb : (which == 1 ? g_Kb : g_Vb);
    const float sc = (which == 0) ? 0.125f : 1.0f;

    #pragma unroll
    for (int mt = 0; mt < 4; mt++) {
        int row = m0 + wm*64 + mt*16 + g;
        #pragma unroll
        for (int nt = 0; nt < 4; nt++) {
            int col = n0 + wn*32 + nt*8 + 2*t;
            float2 bv = *(const float2*)&bias[col];
            float v0 = acc[mt][nt][0] + bv.x, v1 = acc[mt][nt][1] + bv.y;
            float v2 = acc[mt][nt][2] + bv.x, v3 = acc[mt][nt][3] + bv.y;
            if (ADD_RES) {
                float2 r0 = *(const float2*)&res[(size_t)row*DM_ + col];
                float2 r1 = *(const float2*)&res[(size_t)(row+8)*DM_ + col];
                v0 += r0.x; v1 += r0.y; v2 += r1.x; v3 += r1.y;
                *(float2*)&g_x[(size_t)row*DM_ + col]     = make_float2(v0, v1);
                *(float2*)&g_x[(size_t)(row+8)*DM_ + col] = make_float2(v2, v3);
            } else {
                Cb[((size_t)row*DM_ + col) >> 1]     = packbf(v0*sc, v1*sc);
                Cb[((size_t)(row+8)*DM_ + col) >> 1] = packbf(v2*sc, v3*sc);
            }
        }
    }
}

// ---------------------------------------------------------------------------
// Flash attention, bf16 m16n8k16, register-resident P, cp.async double-buffer.
// Q/K/V already bf16 in global: fill = pure cp.async (no temp regs, no cvt).
// smem rows 128B data + 16B pad (stride 144B): LDSM phases conflict-free.
// Mask via g_mbits; all-ones tiles skip apply entirely.
// Block = 128 threads (4 warps), 64 q-rows, 64-key tiles. smem 36.9 KB.
// (R15 flash measured ~180-190us by subtraction — unchanged this round.)
// ---------------------------------------------------------------------------
#define KVST   144
#define KVTILE (64*KVST)

__global__ __launch_bounds__(128)
void flash_tc()
{
    __shared__ __align__(16) unsigned char smemb[4*KVTILE];  // K0 | K1 | V0 | V1
    const unsigned sb = (unsigned)__cvta_generic_to_shared(smemb);

    const int tid = threadIdx.x;
    const int warp = tid >> 5, lane = tid & 31;
    const int g = lane >> 2, t = lane & 3;
    const int q0 = blockIdx.x * 64;
    const int bh = blockIdx.y, b = bh >> 4, h = bh & 15;
    const int wq = warp * 16;

    // fill assignment: half-row (64B) per thread
    const int fr = tid >> 1;
    const int fc = (tid & 1) * 64;
    const unsigned fdst = fr*KVST + fc;

    const char* qsrc = (const char*)g_Qb + ((size_t)(b*S_ + q0 + fr)*DM_ + h*HD_)*2 + fc;
    const char* ksrc = (const char*)g_Kb + ((size_t)(b*S_ + fr)*DM_ + h*HD_)*2 + fc;
    const char* vsrc = (const char*)g_Vb + ((size_t)(b*S_ + fr)*DM_ + h*HD_)*2 + fc;

    // Stage Q into buffer K1 (group 0), KV tile 0 into K0/V0 (group 1).
    #pragma unroll
    for (int j = 0; j < 4; j++)
        cpa16s(sb + KVTILE + fdst + j*16, qsrc + j*16);
    CP_COMMIT();
    #pragma unroll
    for (int j = 0; j < 4; j++) {
        cpa16s(sb + fdst + j*16,            ksrc + j*16);
        cpa16s(sb + 2*KVTILE + fdst + j*16, vsrc + j*16);
    }
    CP_COMMIT();

    CP_WAIT(1);
    __syncthreads();

    // qf via ldmatrix from staged Q (buffer K1)
    unsigned qf[4][4];
    {
        unsigned qbase = sb + KVTILE
            + (wq + (lane & 7) + ((lane >> 3) & 1)*8)*KVST + ((lane >> 4) & 1)*16;
        #pragma unroll
        for (int ks = 0; ks < 4; ks++)
            LDSM4(qf[ks][0], qf[ks][1], qf[ks][2], qf[ks][3], qbase + ks*32);
    }

    float o[8][4];
    #pragma unroll
    for (int nt = 0; nt < 8; nt++)
        #pragma unroll
        for (int i = 0; i < 4; i++) o[nt][i] = 0.f;
    float mi[2] = {-1e30f, -1e30f}, li[2] = {0.f, 0.f};

    const unsigned long long* mrow = g_mbits + (size_t)(b*S_ + q0 + wq + g)*32;

    const unsigned kladdr = ((lane & 7) + ((lane >> 4) & 1)*8)*KVST + ((lane >> 3) & 1)*16;
    const unsigned vladdr = ((lane & 7) + ((lane >> 3) & 1)*8)*KVST + ((lane >> 4) & 1)*16;

    for (int i = 0; i < 32; i++) {
        CP_WAIT(0);
        __syncthreads();   // all copies landed AND prev compute done

        const unsigned off = (i & 1) ? KVTILE : 0u;
        if (i + 1 < 32) {
            const unsigned noff = (i & 1) ? 0u : KVTILE;
            const char* nk = ksrc + (size_t)(i + 1)*64*(DM_*2);
            const char* nv = vsrc + (size_t)(i + 1)*64*(DM_*2);
            #pragma unroll
            for (int j = 0; j < 4; j++) {
                cpa16s(sb + noff + fdst + j*16,            nk + j*16);
                cpa16s(sb + 2*KVTILE + noff + fdst + j*16, nv + j*16);
            }
            CP_COMMIT();
        }

        const unsigned Kbuf = sb + off;
        const unsigned Vbuf = sb + 2*KVTILE + off;

        // S = Q K^T
        float s[8][4];
        #pragma unroll
        for (int nt = 0; nt < 8; nt++)
            #pragma unroll
            for (int ii = 0; ii < 4; ii++) s[nt][ii] = 0.f;

        #pragma unroll
        for (int ks = 0; ks < 4; ks++) {
            #pragma unroll
            for (int ntp = 0; ntp < 4; ntp++) {
                unsigned k0r, k1r, k2r, k3r;
                LDSM4(k0r, k1r, k2r, k3r, Kbuf + kladdr + ntp*16*KVST + ks*32);
                mma16(s[2*ntp],   qf[ks], k0r, k1r);
                mma16(s[2*ntp+1], qf[ks], k2r, k3r);
            }
        }

        // Mask (bitmask; all-ones tiles skip)
        {
            unsigned long long mb0 = mrow[i];
            unsigned long long mb1 = mrow[8*32 + i];
            if (mb0 != ~0ull) {
                #pragma unroll
                for (int nt = 0; nt < 8; nt++) {
                    if (!((mb0 >> (nt*8 + 2*t))     & 1)) s[nt][0] = -1e9f;
                    if (!((mb0 >> (nt*8 + 2*t + 1)) & 1)) s[nt][1] = -1e9f;
                }
            }
            if (mb1 != ~0ull) {
                #pragma unroll
                for (int nt = 0; nt < 8; nt++) {
                    if (!((mb1 >> (nt*8 + 2*t))     & 1)) s[nt][2] = -1e9f;
                    if (!((mb1 >> (nt*8 + 2*t + 1)) & 1)) s[nt][3] = -1e9f;
                }
            }
        }

        // Online softmax (rows g, g+8)
        #pragma unroll
        for (int rr = 0; rr < 2; rr++) {
            float mx = -1e30f;
            #pragma unroll
            for (int nt = 0; nt < 8; nt++)
                mx = fmaxf(mx, fmaxf(s[nt][2*rr], s[nt][2*rr+1]));
            mx = fmaxf(mx, __shfl_xor_sync(0xffffffffu, mx, 1));
            mx = fmaxf(mx, __shfl_xor_sync(0xffffffffu, mx, 2));
            float mnew = fmaxf(mi[rr], mx);
            float alpha = __expf(mi[rr] - mnew);
            float sum = 0.f;
            #pragma unroll
            for (int nt = 0; nt < 8; nt++) {
                s[nt][2*rr]   = __expf(s[nt][2*rr]   - mnew);
                s[nt][2*rr+1] = __expf(s[nt][2*rr+1] - mnew);
                sum += s[nt][2*rr] + s[nt][2*rr+1];
            }
            sum += __shfl_xor_sync(0xffffffffu, sum, 1);
            sum += __shfl_xor_sync(0xffffffffu, sum, 2);
            li[rr] = li[rr]*alpha + sum;
            mi[rr] = mnew;
            #pragma unroll
            for (int nt = 0; nt < 8; nt++) {
                o[nt][2*rr]   *= alpha;
                o[nt][2*rr+1] *= alpha;
            }
        }

        // O += P V : P packed from C-frags in registers
        #pragma unroll
        for (int ks = 0; ks < 4; ks++) {
            unsigned pa[4];
            pa[0] = packbf(s[2*ks][0],   s[2*ks][1]);
            pa[1] = packbf(s[2*ks][2],   s[2*ks][3]);
            pa[2] = packbf(s[2*ks+1][0], s[2*ks+1][1]);
            pa[3] = packbf(s[2*ks+1][2], s[2*ks+1][3]);
            #pragma unroll
            for (int ntp = 0; ntp < 4; ntp++) {
                unsigned v0r, v1r, v2r, v3r;
                LDSM4T(v0r, v1r, v2r, v3r, Vbuf + vladdr + ks*16*KVST + ntp*32);
                mma16(o[2*ntp],   pa, v0r, v1r);
                mma16(o[2*ntp+1], pa, v2r, v3r);
            }
        }
    }

    // Epilogue
    float inv0 = 1.f / li[0], inv1 = 1.f / li[1];
    float* dst0 = g_attn + ((size_t)(b*S_ + q0 + wq + g))*DM_ + h*HD_;
    float* dst1 = dst0 + (size_t)8*DM_;
    #pragma unroll
    for (int nt = 0; nt < 8; nt++) {
        int c = nt*8 + 2*t;
        *(float2*)&dst0[c] = make_float2(o[nt][0]*inv0, o[nt][1]*inv0);
        *(float2*)&dst1[c] = make_float2(o[nt][2]*inv1, o[nt][3]*inv1);
    }
}

// ---------------------------------------------------------------------------
// LayerNorm: unbiased std (ddof=1), denominator (std + eps). One block per row.
// ---------------------------------------------------------------------------
__global__ __launch_bounds__(256)
void layernorm(const float* __restrict__ gamma, const float* __restrict__ beta,
               float* __restrict__ out)
{
    __shared__ float red[2][8];
    const int row = blockIdx.x;
    const int tid = threadIdx.x;
    const float* xr = g_x + (size_t)row * DM_;
    const int c = tid * 4;

    float4 xv = *(const float4*)(xr + c);
    float sum = xv.x + xv.y + xv.z + xv.w;
    float sq  = xv.x*xv.x + xv.y*xv.y + xv.z*xv.z + xv.w*xv.w;

    #pragma unroll
    for (int off = 16; off > 0; off >>= 1) {
        sum += __shfl_xor_sync(0xffffffffu, sum, off);
        sq  += __shfl_xor_sync(0xffffffffu, sq,  off);
    }
    const int w = tid >> 5, lane = tid & 31;
    if (lane == 0) { red[0][w] = sum; red[1][w] = sq; }
    __syncthreads();
    if (tid == 0) {
        float s = 0.f, q = 0.f;
        #pragma unroll
        for (int i = 0; i < 8; i++) { s += red[0][i]; q += red[1][i]; }
        red[0][0] = s; red[1][0] = q;
    }
    __syncthreads();
    sum = red[0][0]; sq = red[1][0];

    float mean = sum / (float)DM_;
    float var  = (sq - (float)DM_ * mean * mean) / (float)(DM_ - 1);
    var = fmaxf(var, 0.f);
    float inv = 1.f / (sqrtf(var) + 1e-6f);

    float4 g4 = *(const float4*)(gamma + c);
    float4 b4 = *(const float4*)(beta + c);
    float4 ov;
    ov.x = g4.x * (xv.x - mean) * inv + b4.x;
    ov.y = g4.y * (xv.y - mean) * inv + b4.y;
    ov.z = g4.z * (xv.z - mean) * inv + b4.z;
    ov.w = g4.w * (xv.w - mean) * inv + b4.w;
    *(float4*)(out + (size_t)row * DM_ + c) = ov;
}

// ---------------------------------------------------------------------------
extern "C" void kernel_launch(void* const* d_in, const int* in_sizes, int n_in,
                              void* d_out, int out_size)
{
    (void)in_sizes; (void)n_in; (void)out_size;
    const float* query = (const float*)d_in[0];
    const float* key_  = (const float*)d_in[1];
    const float* value = (const float*)d_in[2];
    const int*   mask  = (const int*)  d_in[3];
    const float* Wq = (const float*)d_in[4];
    const float* bq = (const float*)d_in[5];
    const float* Wk = (const float*)d_in[6];
    const float* bk = (const float*)d_in[7];
    const float* Wv = (const float*)d_in[8];
    const float* bv = (const float*)d_in[9];
    const float* Wo = (const float*)d_in[10];
    const float* bo = (const float*)d_in[11];
    const float* gamma = (const float*)d_in[12];
    const float* beta  = (const float*)d_in[13];
    float* out = (float*)d_out;

    mask_bits<<<(B_*S_*32 + 255)/256, 256>>>(mask);

    dim3 gg(DM_/128, MTOT/128);   // (8, 32)
    tgemm<false><<<gg, 256>>>(query, Wq, bq, nullptr, 0);
    tgemm<false><<<gg, 256>>>(key_,  Wk, bk, nullptr, 1);
    tgemm<false><<<gg, 256>>>(value, Wv, bv, nullptr, 2);

    flash_tc<<<dim3(S_/64, B_*H_), 128>>>();

    tgemm<true><<<gg, 256>>>(nullptr, Wo, bo, query, 3);

    layernorm<<<MTOT, 256>>>(gamma, beta, out);
}

// round 17
// speedup vs baseline: 1.2475x; 1.0558x over previous
#include <cuda_runtime.h>
#include <math.h>

#define B_   2
#define S_   2048
#define DM_  1024
#define H_   16
#define HD_  64
#define MTOT (B_*S_)

// Scratch (alloc-free rule: __device__ globals)
__device__ unsigned g_Qb[MTOT*DM_/2];   // bf16x2 packed, Q pre-scaled by 0.125
__device__ unsigned g_Kb[MTOT*DM_/2];
__device__ unsigned g_Vb[MTOT*DM_/2];
__device__ float    g_attn[MTOT*DM_];
__device__ float    g_x[MTOT*DM_];
__device__ unsigned long long g_mbits[(size_t)B_*S_*32];  // mask bits per 64-key tile

// pack two fp32 -> bf16x2 (lo = first arg, hi = second arg)
__device__ __forceinline__ unsigned packbf(float lo, float hi) {
    unsigned r; asm("cvt.rn.bf16x2.f32 %0, %1, %2;" : "=r"(r) : "f"(hi), "f"(lo));
    return r;
}

// bf16 m16n8k16 mma, fp32 accumulate (in-place)
__device__ __forceinline__ void mma16(float* d, const unsigned* a, unsigned b0, unsigned b1) {
    asm volatile("mma.sync.aligned.m16n8k16.row.col.f32.bf16.bf16.f32 "
        "{%0,%1,%2,%3}, {%4,%5,%6,%7}, {%8,%9}, {%0,%1,%2,%3};"
        : "+f"(d[0]), "+f"(d[1]), "+f"(d[2]), "+f"(d[3])
        : "r"(a[0]), "r"(a[1]), "r"(a[2]), "r"(a[3]),
          "r"(b0), "r"(b1));
}

#define LDSM4(r0,r1,r2,r3, addr) \
    asm volatile("ldmatrix.sync.aligned.m8n8.x4.shared.b16 {%0,%1,%2,%3}, [%4];" \
        : "=r"(r0), "=r"(r1), "=r"(r2), "=r"(r3) : "r"(addr))
#define LDSM4T(r0,r1,r2,r3, addr) \
    asm volatile("ldmatrix.sync.aligned.m8n8.x4.trans.shared.b16 {%0,%1,%2,%3}, [%4];" \
        : "=r"(r0), "=r"(r1), "=r"(r2), "=r"(r3) : "r"(addr))

__device__ __forceinline__ void cpa16s(unsigned sa, const void* g) {
    asm volatile("cp.async.ca.shared.global [%0], [%1], 16;" :: "r"(sa), "l"(g));
}
#define CP_COMMIT() asm volatile("cp.async.commit_group;")
#define CP_WAIT(N)  asm volatile("cp.async.wait_group %0;" :: "n"(N))

// ---------------------------------------------------------------------------
// Mask -> bitmask pre-pass (unchanged).
// ---------------------------------------------------------------------------
__global__ __launch_bounds__(256)
void mask_bits(const int* __restrict__ mask)
{
    int gw = (blockIdx.x * blockDim.x + threadIdx.x) >> 5;
    int lane = threadIdx.x & 31;
    if (gw >= B_*S_) return;
    const int* row = mask + (size_t)gw * S_;
    for (int kt = 0; kt < 32; kt++) {
        int m0 = row[kt*64 + lane];
        int m1 = row[kt*64 + 32 + lane];
        unsigned b0 = __ballot_sync(0xffffffffu, m0 != 0);
        unsigned b1 = __ballot_sync(0xffffffffu, m1 != 0);
        if (lane == 0)
            g_mbits[(size_t)gw*32 + kt] =
                (unsigned long long)b0 | ((unsigned long long)b1 << 32);
    }
}

// ---------------------------------------------------------------------------
// bf16 tensor-core GEMM (NT): C[m][n] = sum_k A[m][k]*W[n][k] + bias[n] (+res).
// 128x128 tile, BK=32, 256 threads (8 warps 2x4), warp tile 64x32.
// smem bf16x2, stride 20 uints (80B): LDSM phase starts {20r mod 32} tile all
// 32 banks -> conflict-free fragment loads. m16n8k16 mma: half the MMAs and
// 8x fewer shared-load issues vs the tf32 version (R16: issue=24.5% bound).
// Epilogue: bf16x2 stores for Q/K/V (Q pre-scaled 0.125), fp32+res for out.
// ---------------------------------------------------------------------------
#define GST 20

template<bool ADD_RES>
__global__ __launch_bounds__(256, 2)
void tgemm(const float* __restrict__ A, const float* __restrict__ W,
           const float* __restrict__ bias, const float* __restrict__ res, int which)
{
    __shared__ unsigned As[128*GST];
    __shared__ unsigned Bs[128*GST];
    const unsigned As_sa = (unsigned)__cvta_generic_to_shared(As);
    const unsigned Bs_sa = (unsigned)__cvta_generic_to_shared(Bs);

    const float* Abase = (A == nullptr) ? (const float*)g_attn : A;

    const int tid = threadIdx.x;
    const int warp = tid >> 5, lane = tid & 31;
    const int g = lane >> 2, t = lane & 3;
    const int wm = warp >> 2, wn = warp & 3;
    const int m0 = blockIdx.y * 128, n0 = blockIdx.x * 128;

    // fill: 2 threads per row, 16 floats (64B) each -> 8 packed uints
    const int fr = tid >> 1, fh = tid & 1;
    const float* Ag = Abase + (size_t)(m0 + fr)*DM_ + fh*16;
    const float* Wg = W     + (size_t)(n0 + fr)*DM_ + fh*16;
    unsigned* Asrow = &As[fr*GST + fh*8];
    unsigned* Bsrow = &Bs[fr*GST + fh*8];

    // ldmatrix per-lane base offsets (bytes)
    // A-frag (like flash qbase): rows via (lane>>3)&1, k-chunk via (lane>>4)&1
    const unsigned aoff = ((lane & 7) + ((lane >> 3) & 1)*8)*GST*4 + ((lane >> 4) & 1)*16;
    // B-frag (like flash kladdr): rows via (lane>>4)&1, k-chunk via (lane>>3)&1
    const unsigned boff = ((lane & 7) + ((lane >> 4) & 1)*8)*GST*4 + ((lane >> 3) & 1)*16;

    float acc[4][4][4];
    #pragma unroll
    for (int mt = 0; mt < 4; mt++)
        #pragma unroll
        for (int nt = 0; nt < 4; nt++)
            #pragma unroll
            for (int i = 0; i < 4; i++) acc[mt][nt][i] = 0.f;

    for (int k0 = 0; k0 < DM_; k0 += 32) {
        __syncthreads();
        {
            float4 a0 = *(const float4*)(Ag + k0);
            float4 a1 = *(const float4*)(Ag + k0 + 4);
            float4 a2 = *(const float4*)(Ag + k0 + 8);
            float4 a3 = *(const float4*)(Ag + k0 + 12);
            float4 w0 = *(const float4*)(Wg + k0);
            float4 w1 = *(const float4*)(Wg + k0 + 4);
            float4 w2 = *(const float4*)(Wg + k0 + 8);
            float4 w3 = *(const float4*)(Wg + k0 + 12);
            uint4 ua, ub;
            ua.x = packbf(a0.x, a0.y); ua.y = packbf(a0.z, a0.w);
            ua.z = packbf(a1.x, a1.y); ua.w = packbf(a1.z, a1.w);
            *(uint4*)Asrow = ua;
            ua.x = packbf(a2.x, a2.y); ua.y = packbf(a2.z, a2.w);
            ua.z = packbf(a3.x, a3.y); ua.w = packbf(a3.z, a3.w);
            *(uint4*)(Asrow + 4) = ua;
            ub.x = packbf(w0.x, w0.y); ub.y = packbf(w0.z, w0.w);
            ub.z = packbf(w1.x, w1.y); ub.w = packbf(w1.z, w1.w);
            *(uint4*)Bsrow = ub;
            ub.x = packbf(w2.x, w2.y); ub.y = packbf(w2.z, w2.w);
            ub.z = packbf(w3.x, w3.y); ub.w = packbf(w3.z, w3.w);
            *(uint4*)(Bsrow + 4) = ub;
        }
        __syncthreads();

        #pragma unroll
        for (int ks = 0; ks < 2; ks++) {
            unsigned af[4][4], bf[2][4];
            #pragma unroll
            for (int mt = 0; mt < 4; mt++) {
                unsigned addr = As_sa + (wm*64 + mt*16)*GST*4 + ks*32 + aoff;
                LDSM4(af[mt][0], af[mt][1], af[mt][2], af[mt][3], addr);
            }
            #pragma unroll
            for (int np = 0; np < 2; np++) {
                unsigned addr = Bs_sa + (wn*32 + np*16)*GST*4 + ks*32 + boff;
                LDSM4(bf[np][0], bf[np][1], bf[np][2], bf[np][3], addr);
            }
            #pragma unroll
            for (int mt = 0; mt < 4; mt++)
                #pragma unroll
                for (int np = 0; np < 2; np++) {
                    mma16(acc[mt][2*np],   af[mt], bf[np][0], bf[np][1]);
                    mma16(acc[mt][2*np+1], af[mt], bf[np][2], bf[np][3]);
                }
        }
    }

    unsigned* Cb = (which == 0) ? g_Qb : (which == 1 ? g_Kb : g_Vb);
    const float sc = (which == 0) ? 0.125f : 1.0f;

    #pragma unroll
    for (int mt = 0; mt < 4; mt++) {
        int row = m0 + wm*64 + mt*16 + g;
        #pragma unroll
        for (int nt = 0; nt < 4; nt++) {
            int col = n0 + wn*32 + nt*8 + 2*t;
            float2 bv = *(const float2*)&bias[col];
            float v0 = acc[mt][nt][0] + bv.x, v1 = acc[mt][nt][1] + bv.y;
            float v2 = acc[mt][nt][2] + bv.x, v3 = acc[mt][nt][3] + bv.y;
            if (ADD_RES) {
                float2 r0 = *(const float2*)&res[(size_t)row*DM_ + col];
                float2 r1 = *(const float2*)&res[(size_t)(row+8)*DM_ + col];
                v0 += r0.x; v1 += r0.y; v2 += r1.x; v3 += r1.y;
                *(float2*)&g_x[(size_t)row*DM_ + col]     = make_float2(v0, v1);
                *(float2*)&g_x[(size_t)(row+8)*DM_ + col] = make_float2(v2, v3);
            } else {
                Cb[((size_t)row*DM_ + col) >> 1]     = packbf(v0*sc, v1*sc);
                Cb[((size_t)(row+8)*DM_ + col) >> 1] = packbf(v2*sc, v3*sc);
            }
        }
    }
}

// ---------------------------------------------------------------------------
// Flash attention — R15/R16 body unchanged (measured ~185us).
// ---------------------------------------------------------------------------
#define KVST   144
#define KVTILE (64*KVST)

__global__ __launch_bounds__(128)
void flash_tc()
{
    __shared__ __align__(16) unsigned char smemb[4*KVTILE];  // K0 | K1 | V0 | V1
    const unsigned sb = (unsigned)__cvta_generic_to_shared(smemb);

    const int tid = threadIdx.x;
    const int warp = tid >> 5, lane = tid & 31;
    const int g = lane >> 2, t = lane & 3;
    const int q0 = blockIdx.x * 64;
    const int bh = blockIdx.y, b = bh >> 4, h = bh & 15;
    const int wq = warp * 16;

    const int fr = tid >> 1;
    const int fc = (tid & 1) * 64;
    const unsigned fdst = fr*KVST + fc;

    const char* qsrc = (const char*)g_Qb + ((size_t)(b*S_ + q0 + fr)*DM_ + h*HD_)*2 + fc;
    const char* ksrc = (const char*)g_Kb + ((size_t)(b*S_ + fr)*DM_ + h*HD_)*2 + fc;
    const char* vsrc = (const char*)g_Vb + ((size_t)(b*S_ + fr)*DM_ + h*HD_)*2 + fc;

    #pragma unroll
    for (int j = 0; j < 4; j++)
        cpa16s(sb + KVTILE + fdst + j*16, qsrc + j*16);
    CP_COMMIT();
    #pragma unroll
    for (int j = 0; j < 4; j++) {
        cpa16s(sb + fdst + j*16,            ksrc + j*16);
        cpa16s(sb + 2*KVTILE + fdst + j*16, vsrc + j*16);
    }
    CP_COMMIT();

    CP_WAIT(1);
    __syncthreads();

    unsigned qf[4][4];
    {
        unsigned qbase = sb + KVTILE
            + (wq + (lane & 7) + ((lane >> 3) & 1)*8)*KVST + ((lane >> 4) & 1)*16;
        #pragma unroll
        for (int ks = 0; ks < 4; ks++)
            LDSM4(qf[ks][0], qf[ks][1], qf[ks][2], qf[ks][3], qbase + ks*32);
    }

    float o[8][4];
    #pragma unroll
    for (int nt = 0; nt < 8; nt++)
        #pragma unroll
        for (int i = 0; i < 4; i++) o[nt][i] = 0.f;
    float mi[2] = {-1e30f, -1e30f}, li[2] = {0.f, 0.f};

    const unsigned long long* mrow = g_mbits + (size_t)(b*S_ + q0 + wq + g)*32;

    const unsigned kladdr = ((lane & 7) + ((lane >> 4) & 1)*8)*KVST + ((lane >> 3) & 1)*16;
    const unsigned vladdr = ((lane & 7) + ((lane >> 3) & 1)*8)*KVST + ((lane >> 4) & 1)*16;

    for (int i = 0; i < 32; i++) {
        CP_WAIT(0);
        __syncthreads();

        const unsigned off = (i & 1) ? KVTILE : 0u;
        if (i + 1 < 32) {
            const unsigned noff = (i & 1) ? 0u : KVTILE;
            const char* nk = ksrc + (size_t)(i + 1)*64*(DM_*2);
            const char* nv = vsrc + (size_t)(i + 1)*64*(DM_*2);
            #pragma unroll
            for (int j = 0; j < 4; j++) {
                cpa16s(sb + noff + fdst + j*16,            nk + j*16);
                cpa16s(sb + 2*KVTILE + noff + fdst + j*16, nv + j*16);
            }
            CP_COMMIT();
        }

        const unsigned Kbuf = sb + off;
        const unsigned Vbuf = sb + 2*KVTILE + off;

        float s[8][4];
        #pragma unroll
        for (int nt = 0; nt < 8; nt++)
            #pragma unroll
            for (int ii = 0; ii < 4; ii++) s[nt][ii] = 0.f;

        #pragma unroll
        for (int ks = 0; ks < 4; ks++) {
            #pragma unroll
            for (int ntp = 0; ntp < 4; ntp++) {
                unsigned k0r, k1r, k2r, k3r;
                LDSM4(k0r, k1r, k2r, k3r, Kbuf + kladdr + ntp*16*KVST + ks*32);
                mma16(s[2*ntp],   qf[ks], k0r, k1r);
                mma16(s[2*ntp+1], qf[ks], k2r, k3r);
            }
        }

        {
            unsigned long long mb0 = mrow[i];
            unsigned long long mb1 = mrow[8*32 + i];
            if (mb0 != ~0ull) {
                #pragma unroll
                for (int nt = 0; nt < 8; nt++) {
                    if (!((mb0 >> (nt*8 + 2*t))     & 1)) s[nt][0] = -1e9f;
                    if (!((mb0 >> (nt*8 + 2*t + 1)) & 1)) s[nt][1] = -1e9f;
                }
            }
            if (mb1 != ~0ull) {
                #pragma unroll
                for (int nt = 0; nt < 8; nt++) {
                    if (!((mb1 >> (nt*8 + 2*t))     & 1)) s[nt][2] = -1e9f;
                    if (!((mb1 >> (nt*8 + 2*t + 1)) & 1)) s[nt][3] = -1e9f;
                }
            }
        }

        #pragma unroll
        for (int rr = 0; rr < 2; rr++) {
            float mx = -1e30f;
            #pragma unroll
            for (int nt = 0; nt < 8; nt++)
                mx = fmaxf(mx, fmaxf(s[nt][2*rr], s[nt][2*rr+1]));
            mx = fmaxf(mx, __shfl_xor_sync(0xffffffffu, mx, 1));
            mx = fmaxf(mx, __shfl_xor_sync(0xffffffffu, mx, 2));
            float mnew = fmaxf(mi[rr], mx);
            float alpha = __expf(mi[rr] - mnew);
            float sum = 0.f;
            #pragma unroll
            for (int nt = 0; nt < 8; nt++) {
                s[nt][2*rr]   = __expf(s[nt][2*rr]   - mnew);
                s[nt][2*rr+1] = __expf(s[nt][2*rr+1] - mnew);
                sum += s[nt][2*rr] + s[nt][2*rr+1];
            }
            sum += __shfl_xor_sync(0xffffffffu, sum, 1);
            sum += __shfl_xor_sync(0xffffffffu, sum, 2);
            li[rr] = li[rr]*alpha + sum;
            mi[rr] = mnew;
            #pragma unroll
            for (int nt = 0; nt < 8; nt++) {
                o[nt][2*rr]   *= alpha;
                o[nt][2*rr+1] *= alpha;
            }
        }

        #pragma unroll
        for (int ks = 0; ks < 4; ks++) {
            unsigned pa[4];
            pa[0] = packbf(s[2*ks][0],   s[2*ks][1]);
            pa[1] = packbf(s[2*ks][2],   s[2*ks][3]);
            pa[2] = packbf(s[2*ks+1][0], s[2*ks+1][1]);
            pa[3] = packbf(s[2*ks+1][2], s[2*ks+1][3]);
            #pragma unroll
            for (int ntp = 0; ntp < 4; ntp++) {
                unsigned v0r, v1r, v2r, v3r;
                LDSM4T(v0r, v1r, v2r, v3r, Vbuf + vladdr + ks*16*KVST + ntp*32);
                mma16(o[2*ntp],   pa, v0r, v1r);
                mma16(o[2*ntp+1], pa, v2r, v3r);
            }
        }
    }

    float inv0 = 1.f / li[0], inv1 = 1.f / li[1];
    float* dst0 = g_attn + ((size_t)(b*S_ + q0 + wq + g))*DM_ + h*HD_;
    float* dst1 = dst0 + (size_t)8*DM_;
    #pragma unroll
    for (int nt = 0; nt < 8; nt++) {
        int c = nt*8 + 2*t;
        *(float2*)&dst0[c] = make_float2(o[nt][0]*inv0, o[nt][1]*inv0);
        *(float2*)&dst1[c] = make_float2(o[nt][2]*inv1, o[nt][3]*inv1);
    }
}

// ---------------------------------------------------------------------------
// LayerNorm (unchanged).
// ---------------------------------------------------------------------------
__global__ __launch_bounds__(256)
void layernorm(const float* __restrict__ gamma, const float* __restrict__ beta,
               float* __restrict__ out)
{
    __shared__ float red[2][8];
    const int row = blockIdx.x;
    const int tid = threadIdx.x;
    const float* xr = g_x + (size_t)row * DM_;
    const int c = tid * 4;

    float4 xv = *(const float4*)(xr + c);
    float sum = xv.x + xv.y + xv.z + xv.w;
    float sq  = xv.x*xv.x + xv.y*xv.y + xv.z*xv.z + xv.w*xv.w;

    #pragma unroll
    for (int off = 16; off > 0; off >>= 1) {
        sum += __shfl_xor_sync(0xffffffffu, sum, off);
        sq  += __shfl_xor_sync(0xffffffffu, sq,  off);
    }
    const int w = tid >> 5, lane = tid & 31;
    if (lane == 0) { red[0][w] = sum; red[1][w] = sq; }
    __syncthreads();
    if (tid == 0) {
        float s = 0.f, q = 0.f;
        #pragma unroll
        for (int i = 0; i < 8; i++) { s += red[0][i]; q += red[1][i]; }
        red[0][0] = s; red[1][0] = q;
    }
    __syncthreads();
    sum = red[0][0]; sq = red[1][0];

    float mean = sum / (float)DM_;
    float var  = (sq - (float)DM_ * mean * mean) / (float)(DM_ - 1);
    var = fmaxf(var, 0.f);
    float inv = 1.f / (sqrtf(var) + 1e-6f);

    float4 g4 = *(const float4*)(gamma + c);
    float4 b4 = *(const float4*)(beta + c);
    float4 ov;
    ov.x = g4.x * (xv.x - mean) * inv + b4.x;
    ov.y = g4.y * (xv.y - mean) * inv + b4.y;
    ov.z = g4.z * (xv.z - mean) * inv + b4.z;
    ov.w = g4.w * (xv.w - mean) * inv + b4.w;
    *(float4*)(out + (size_t)row * DM_ + c) = ov;
}

// ---------------------------------------------------------------------------
extern "C" void kernel_launch(void* const* d_in, const int* in_sizes, int n_in,
                              void* d_out, int out_size)
{
    (void)in_sizes; (void)n_in; (void)out_size;
    const float* query = (const float*)d_in[0];
    const float* key_  = (const float*)d_in[1];
    const float* value = (const float*)d_in[2];
    const int*   mask  = (const int*)  d_in[3];
    const float* Wq = (const float*)d_in[4];
    const float* bq = (const float*)d_in[5];
    const float* Wk = (const float*)d_in[6];
    const float* bk = (const float*)d_in[7];
    const float* Wv = (const float*)d_in[8];
    const float* bv = (const float*)d_in[9];
    const float* Wo = (const float*)d_in[10];
    const float* bo = (const float*)d_in[11];
    const float* gamma = (const float*)d_in[12];
    const float* beta  = (const float*)d_in[13];
    float* out = (float*)d_out;

    mask_bits<<<(B_*S_*32 + 255)/256, 256>>>(mask);

    dim3 gg(DM_/128, MTOT/128);   // (8, 32)
    tgemm<false><<<gg, 256>>>(query, Wq, bq, nullptr, 0);
    tgemm<false><<<gg, 256>>>(key_,  Wk, bk, nullptr, 1);
    tgemm<false><<<gg, 256>>>(value, Wv, bv, nullptr, 2);

    flash_tc<<<dim3(S_/64, B_*H_), 128>>>();

    tgemm<true><<<gg, 256>>>(nullptr, Wo, bo, query, 3);

    layernorm<<<MTOT, 256>>>(gamma, beta, out);
}